// round 9
// baseline (speedup 1.0000x reference)
#include <cuda_runtime.h>
#include <math.h>

// x,y: (B=2, C=6, H=512, W=512) fp32. Output: (B,1,H,W,2) fp32, trailing = radius {2,4}.
#define BATCH 2
#define CH    6
#define HH    512
#define WW    512
#define EPSV  1e-6f

#define TX     32
#define TYT    8
#define NROWS  4
#define TILE_H (TYT * NROWS)   // 32

typedef unsigned long long u64;
union PF { u64 u; float2 f; };

#define NEG1_2 0xBF800000BF800000ull   // (-1.0f, -1.0f)

__device__ __forceinline__ u64 fma2(u64 a, u64 b, u64 c) {
    u64 d; asm("fma.rn.f32x2 %0, %1, %2, %3;" : "=l"(d) : "l"(a), "l"(b), "l"(c)); return d;
}
__device__ __forceinline__ u64 add2(u64 a, u64 b) {
    u64 d; asm("add.rn.f32x2 %0, %1, %2;" : "=l"(d) : "l"(a), "l"(b)); return d;
}
__device__ __forceinline__ u64 mul2(u64 a, u64 b) {
    u64 d; asm("mul.rn.f32x2 %0, %1, %2;" : "=l"(d) : "l"(a), "l"(b)); return d;
}
__device__ __forceinline__ u64 pack2(float lo, float hi) {
    u64 d; asm("mov.b64 %0, {%1, %2};" : "=l"(d) : "f"(lo), "f"(hi)); return d;
}

__device__ __forceinline__ int refl(int p, int n) {
    if (p < 0) p = -p;
    if (p >= n) p = 2 * n - 2 - p;
    return p;
}

// Packed Cholesky (lower, packed 21) for TWO matrices at once (lo/hi lanes),
// followed by packed lower-triangular inverse into li.
__device__ __forceinline__ void chol_inv6_2(u64 a[21], u64 li[21]) {
    u64 invd[6], ninvd[6];
#pragma unroll
    for (int j = 0; j < 6; j++) {
        u64 d = a[j * (j + 1) / 2 + j];
#pragma unroll
        for (int t = 0; t < j; t++) {
            u64 v = a[j * (j + 1) / 2 + t];
            d = fma2(mul2(v, NEG1_2), v, d);     // d -= v*v (both lanes)
        }
        PF df; df.u = d;
        u64 inv = pack2(rsqrtf(df.f.x), rsqrtf(df.f.y));
        a[j * (j + 1) / 2 + j] = mul2(d, inv);   // sqrt(d) = d * rsqrt(d)
        invd[j] = inv;
        ninvd[j] = mul2(inv, NEG1_2);
#pragma unroll
        for (int i = j + 1; i < 6; i++) {
            u64 s = a[i * (i + 1) / 2 + j];
#pragma unroll
            for (int t = 0; t < j; t++)
                s = fma2(mul2(a[i * (i + 1) / 2 + t], NEG1_2),
                         a[j * (j + 1) / 2 + t], s);
            a[i * (i + 1) / 2 + j] = mul2(s, inv);
        }
    }
#pragma unroll
    for (int j = 0; j < 6; j++) {
        li[j * (j + 1) / 2 + j] = invd[j];
#pragma unroll
        for (int i = j + 1; i < 6; i++) {
            u64 s = 0ull;                         // (0.f, 0.f)
#pragma unroll
            for (int t = j; t < i; t++)
                s = fma2(a[i * (i + 1) / 2 + t], li[t * (t + 1) / 2 + j], s);
            li[i * (i + 1) / 2 + j] = mul2(s, ninvd[i]);  // -s * invd[i]
        }
    }
}

// Accumulate (SUB=false) or subtract (SUB=true) one padded row's horizontal
// k-window of products into the packed accumulators.
template <int K, int CS, bool SUB>
__device__ __forceinline__ void accum_row(
    const u64* __restrict__ s, int off,
    u64* __restrict__ SP, u64* __restrict__ SPP, float* __restrict__ Sxy) {
#pragma unroll
    for (int dx = 0; dx < K; dx++) {
        PF P[6], Pm[6];
#pragma unroll
        for (int c = 0; c < 6; c++) {
            P[c].u = s[c * CS + off + dx];
            Pm[c].u = SUB ? mul2(P[c].u, NEG1_2) : P[c].u;
        }
#pragma unroll
        for (int i = 0; i < 6; i++) SP[i] = add2(SP[i], Pm[i].u);
#pragma unroll
        for (int i = 0; i < 6; i++)
#pragma unroll
            for (int j = 0; j <= i; j++)
                SPP[i * (i + 1) / 2 + j] =
                    fma2(Pm[i].u, P[j].u, SPP[i * (i + 1) / 2 + j]);  // (xx, yy)
#pragma unroll
        for (int i = 0; i < 6; i++)
#pragma unroll
            for (int j = 0; j < 6; j++)
                Sxy[i * 6 + j] = fmaf(Pm[i].f.x, P[j].f.y, Sxy[i * 6 + j]);
    }
}

template <int K>
__device__ __forceinline__ float cca_epilogue(
    const u64* __restrict__ SP, const u64* __restrict__ SPP,
    const float* __restrict__ Sxy) {
    constexpr float ia = 1.0f / (float)(K * K);
    const u64 IA2  = pack2(ia, ia);
    const u64 EPS2 = pack2(EPSV, EPSV);

    PF M[6], Mn[6];
#pragma unroll
    for (int i = 0; i < 6; i++) {
        M[i].u  = mul2(SP[i], IA2);      // (mx, my)
        Mn[i].u = mul2(M[i].u, NEG1_2);
    }

    // A = SPP*ia - M_i*M_j (+eps on diag), packed (cxx | cyy)
    u64 A[21], LI[21];
#pragma unroll
    for (int i = 0; i < 6; i++)
#pragma unroll
        for (int j = 0; j <= i; j++) {
            int t = i * (i + 1) / 2 + j;
            u64 v = fma2(Mn[i].u, M[j].u, mul2(SPP[t], IA2));
            A[t] = (i == j) ? add2(v, EPS2) : v;
        }
    chol_inv6_2(A, LI);

    // cxy scalar (built after chol to shorten A's live range)
    float cxy[36];
#pragma unroll
    for (int i = 0; i < 6; i++)
#pragma unroll
        for (int j = 0; j < 6; j++)
            cxy[i * 6 + j] = fmaf(-M[i].f.x, M[j].f.y, Sxy[i * 6 + j] * ia);

    // diag_d = sum_{j<=d} sum_{k>=d} lxi[d][j] * cxy[j][k] * lyi[k][d]
    float acc = 0.0f;
#pragma unroll
    for (int d = 0; d < 6; d++) {
        float dv = 0.0f;
#pragma unroll
        for (int k = d; k < 6; k++) {
            float t = 0.0f;
#pragma unroll
            for (int j = 0; j <= d; j++) {
                PF l; l.u = LI[d * (d + 1) / 2 + j];
                t = fmaf(l.f.x, cxy[j * 6 + k], t);
            }
            PF r; r.u = LI[k * (k + 1) / 2 + d];
            dv = fmaf(t, r.f.y, dv);
        }
        acc += fabsf(dv);
    }
    return acc * (1.0f / 6.0f);
}

template <int R>
__device__ __forceinline__ void cca_block(
    const float* __restrict__ x, const float* __restrict__ y,
    float* __restrict__ out, int b, int ridx) {
    constexpr int K  = 2 * R + 1;
    constexpr int PW = TX + 2 * R;
    constexpr int PH = TILE_H + 2 * R;
    constexpr int CS = PH * PW;            // per-channel smem stride (pairs)

    extern __shared__ u64 sData[];         // [CH][PH][PW] packed (x, y)

    const int x0 = blockIdx.x * TX;
    const int y0 = blockIdx.y * TILE_H;
    const int tid = threadIdx.y * TX + threadIdx.x;

    // Cooperative load with reflect padding resolved at load.
    for (int i = tid; i < CS; i += TX * TYT) {
        int ty = i / PW;
        int tx = i - ty * PW;
        int gy = refl(y0 + ty - R, HH);
        int gx = refl(x0 + tx - R, WW);
        long base = ((long)b * CH) * HH * WW + (long)gy * WW + gx;
#pragma unroll
        for (int c = 0; c < CH; c++) {
            long g = base + (long)c * HH * WW;
            PF p; p.f = make_float2(x[g], y[g]);
            sData[c * CS + i] = p.u;
        }
    }
    __syncthreads();

    u64 SP[6], SPP[21];
    float Sxy[36];
#pragma unroll
    for (int i = 0; i < 6; i++) SP[i] = 0ull;
#pragma unroll
    for (int i = 0; i < 21; i++) SPP[i] = 0ull;
#pragma unroll
    for (int i = 0; i < 36; i++) Sxy[i] = 0.f;

    const int tx = threadIdx.x;
    const int rb = threadIdx.y * NROWS;    // first output-local row for this thread
    const long outBase = (((long)b * HH + (y0 + rb)) * WW + (x0 + tx)) * 2 + ridx;

#pragma unroll 1
    for (int s = 0; s < NROWS; s++) {
        if (s == 0) {
#pragma unroll 1
            for (int p = 0; p < K; p++)
                accum_row<K, CS, false>(sData, (rb + p) * PW + tx, SP, SPP, Sxy);
        } else {
            accum_row<K, CS, true >(sData, (rb + s - 1) * PW + tx, SP, SPP, Sxy);
            accum_row<K, CS, false>(sData, (rb + s - 1 + K) * PW + tx, SP, SPP, Sxy);
        }
        out[outBase + (long)s * WW * 2] = cca_epilogue<K>(SP, SPP, Sxy);
    }
}

// Merged launch: blockIdx.z = {0,1}: r=2 on batch z; {2,3}: r=4 on batch z-2.
// Same 32x32 output tile for both radii -> uniform grid, mixed-cost wave pool.
__global__ __launch_bounds__(TX * TYT, 2)
void cca_merged(const float* __restrict__ x, const float* __restrict__ y,
                float* __restrict__ out) {
    const int z = blockIdx.z;
    if (z < BATCH) {
        cca_block<2>(x, y, out, z, 0);
    } else {
        cca_block<4>(x, y, out, z - BATCH, 1);
    }
}

extern "C" void kernel_launch(void* const* d_in, const int* in_sizes, int n_in,
                              void* d_out, int out_size) {
    const float* x = (const float*)d_in[0];
    const float* y = (const float*)d_in[1];
    float* out = (float*)d_out;

    // smem sized for the larger (r=4) tile: 6 * 40 * 40 * 8 = 76,800 B
    const size_t smem = sizeof(u64) * CH * (TILE_H + 8) * (TX + 8);
    cudaFuncSetAttribute(cca_merged, cudaFuncAttributeMaxDynamicSharedMemorySize, (int)smem);

    dim3 block(TX, TYT, 1);
    dim3 grid(WW / TX, HH / TILE_H, 2 * BATCH);

    cca_merged<<<grid, block, smem>>>(x, y, out);
}